// round 3
// baseline (speedup 1.0000x reference)
#include <cuda_runtime.h>
#include <cstdint>

#define THREADS 256
#define TM      128        // batch rows per CTA
#define HID     256
#define INP     128
#define CAT     384
#define NCH     24         // K chunks of 16
#define CHW     4096       // words per chunk (256 n x 16 k)
#define CHB     16384      // bytes per chunk

// Pre-converted (tf32, pre-swizzled) weights: [Wz | Wr | Wh], each NCH*CHW words.
__device__ uint32_t wscratch[3 * NCH * CHW];

static __device__ __forceinline__ uint32_t smem_u32(const void* p) {
    uint32_t a;
    asm("{ .reg .u64 t; cvta.to.shared.u64 t, %1; cvt.u32.u64 %0, t; }" : "=r"(a) : "l"(p));
    return a;
}
static __device__ __forceinline__ uint64_t gptr(const void* p) {
    uint64_t r;
    asm("cvta.to.global.u64 %0, %1;" : "=l"(r) : "l"(p));
    return r;
}
static __device__ __forceinline__ uint32_t f2tf32(float v) {
    uint32_t t;
    asm("cvt.rna.tf32.f32 %0, %1;" : "=r"(t) : "f"(v));
    return t;
}
static __device__ __forceinline__ void mma8(float* d, uint32_t a0, uint32_t a1,
                                            uint32_t a2, uint32_t a3,
                                            uint32_t b0, uint32_t b1) {
    asm volatile(
        "mma.sync.aligned.m16n8k8.row.col.f32.tf32.tf32.f32 "
        "{%0,%1,%2,%3}, {%4,%5,%6,%7}, {%8,%9}, {%0,%1,%2,%3};"
        : "+f"(d[0]), "+f"(d[1]), "+f"(d[2]), "+f"(d[3])
        : "r"(a0), "r"(a1), "r"(a2), "r"(a3), "r"(b0), "r"(b1));
}
static __device__ __forceinline__ void cpa16(uint32_t saddr, uint64_t gaddr) {
    asm volatile("cp.async.ca.shared.global [%0], [%1], 16;" :: "r"(saddr), "l"(gaddr) : "memory");
}
#define CP_COMMIT() asm volatile("cp.async.commit_group;" ::: "memory")
#define CP_WAIT(n)  asm volatile("cp.async.wait_group %0;" :: "n"(n) : "memory")

// load one full 16KB chunk: 4 x 16B per thread
static __device__ __forceinline__ void load_chunk(uint32_t sdst, uint64_t gsrc, int tid) {
    #pragma unroll
    for (int u = 0; u < 4; u++)
        cpa16(sdst + u * 4096 + tid * 16, gsrc + (size_t)u * 4096 + (size_t)tid * 16);
    CP_COMMIT();
}

// ---------------- weight pre-conversion: fp32 -> tf32, pre-swizzled chunk image ----------
// chunk layout: word = n*16 + (kl ^ g), g = 4*((n>>1)&3), kl = k - chunk*16
__global__ void preconv_kernel(const float* __restrict__ Wz, const float* __restrict__ Wr,
                               const float* __restrict__ Wh) {
    int gid = blockIdx.x * THREADS + threadIdx.x;
    if (gid >= 3 * NCH * CHW) return;
    int w = gid / (NCH * CHW);
    int rem = gid - w * (NCH * CHW);
    int c = rem >> 12;            // /4096
    int widx = rem & 4095;
    int n = widx >> 4;
    int p = widx & 15;
    int kl = p ^ ((((n >> 1) & 3)) << 2);
    int k = c * 16 + kl;
    const float* W = (w == 0) ? Wz : (w == 1) ? Wr : Wh;
    wscratch[gid] = f2tf32(W[(size_t)n * CAT + k]);
}

// ---------------- one K=384 GEMM pass: acc[128x256 tile, warp 64x64] --------------------
static __device__ __forceinline__ void gemm_pass(
    const uint32_t* Asu, const uint32_t* Bsu, uint32_t bs_byte,
    const uint32_t* wbase, float (&acc)[4][8][4],
    int m0, int n0, int lane, int tid)
{
    #pragma unroll
    for (int mt = 0; mt < 4; mt++)
        #pragma unroll
        for (int nt = 0; nt < 8; nt++)
            #pragma unroll
            for (int q = 0; q < 4; q++) acc[mt][nt][q] = 0.f;

    uint64_t g0 = gptr(wbase);
    load_chunk(bs_byte, g0, tid);

    const int r_base = m0 + (lane >> 2);
    const int kq = lane & 3;

    #pragma unroll 1
    for (int c = 0; c < NCH; c++) {
        if (c + 1 < NCH) {
            load_chunk(bs_byte + ((c + 1) & 1) * CHB, g0 + (size_t)(c + 1) * CHB, tid);
            CP_WAIT(1);
        } else {
            CP_WAIT(0);
        }
        __syncthreads();

        const uint32_t* B = Bsu + (c & 1) * CHW;
        #pragma unroll
        for (int kb = 0; kb < 16; kb += 8) {
            int kk = c * 16 + kb + kq;
            uint32_t bfr[8][2];
            #pragma unroll
            for (int nt = 0; nt < 8; nt++) {
                int n = n0 + nt * 8 + (lane >> 2);
                int g = ((n >> 1) & 3) << 2;
                int kl = kb + kq;
                bfr[nt][0] = B[n * 16 + (kl ^ g)];
                bfr[nt][1] = B[n * 16 + ((kl + 4) ^ g)];
            }
            #pragma unroll
            for (int mt = 0; mt < 4; mt++) {
                int r = r_base + mt * 16;
                int xr = (r & 7) << 2;
                uint32_t a0 = Asu[r * CAT + (kk ^ xr)];
                uint32_t a2 = Asu[r * CAT + ((kk + 4) ^ xr)];
                uint32_t a1 = Asu[(r + 8) * CAT + (kk ^ xr)];
                uint32_t a3 = Asu[(r + 8) * CAT + ((kk + 4) ^ xr)];
                #pragma unroll
                for (int nt = 0; nt < 8; nt++)
                    mma8(acc[mt][nt], a0, a1, a2, a3, bfr[nt][0], bfr[nt][1]);
            }
        }
        __syncthreads();
    }
}

// ---------------- fused GRU kernel ------------------------------------------------------
__global__ void __launch_bounds__(THREADS, 1) gru_main_kernel(
    const float* __restrict__ x, const float* __restrict__ hp,
    const float* __restrict__ bz, const float* __restrict__ br,
    const float* __restrict__ bh, float* __restrict__ out)
{
    extern __shared__ uint32_t sm[];
    uint32_t* Asu = sm;                       // 128*384 words (tf32 ih, XOR-swizzled)
    uint32_t* Bsu = sm + TM * CAT;            // 2 * 4096 words (B double buffer)
    const uint32_t bs_byte = smem_u32(Bsu);

    const int tid  = threadIdx.x;
    const int lane = tid & 31;
    const int warp = tid >> 5;
    const int m0   = (warp >> 2) * 64;
    const int n0   = (warp & 3) * 64;
    const int blockRow = blockIdx.x * TM;

    // ---- fill A smem: tf32(ih), swizzled: word = row*384 + (k ^ (4*(row&7))) ----
    #pragma unroll 1
    for (int it = 0; it < 48; it++) {
        int idx = it * THREADS + tid;          // 0 .. 12287
        int row = idx / 96;
        int c4  = idx - row * 96;
        int k   = c4 * 4;
        const float* src = (k < INP) ? (x + (size_t)(blockRow + row) * INP + k)
                                     : (hp + (size_t)(blockRow + row) * HID + (k - INP));
        float4 v = *reinterpret_cast<const float4*>(src);
        int w0 = row * CAT + (k ^ ((row & 7) << 2));
        uint4 t;
        t.x = f2tf32(v.x); t.y = f2tf32(v.y); t.z = f2tf32(v.z); t.w = f2tf32(v.w);
        *reinterpret_cast<uint4*>(Asu + w0) = t;
    }
    __syncthreads();

    float acc[4][8][4];

    // ================= pass 1: z = hardsigmoid(ih @ Wz^T + bz) -> out (scratch) =========
    gemm_pass(Asu, Bsu, bs_byte, wscratch, acc, m0, n0, lane, tid);
    #pragma unroll
    for (int mt = 0; mt < 4; mt++) {
        int rl = m0 + mt * 16 + (lane >> 2);
        #pragma unroll
        for (int nt = 0; nt < 8; nt++) {
            int cb = n0 + nt * 8 + ((lane & 3) << 1);
            float2 bv = *reinterpret_cast<const float2*>(bz + cb);
            float z0 = __saturatef((acc[mt][nt][0] + bv.x) * 0.16666667f + 0.5f);
            float z1 = __saturatef((acc[mt][nt][1] + bv.y) * 0.16666667f + 0.5f);
            float z2 = __saturatef((acc[mt][nt][2] + bv.x) * 0.16666667f + 0.5f);
            float z3 = __saturatef((acc[mt][nt][3] + bv.y) * 0.16666667f + 0.5f);
            size_t o0 = (size_t)(blockRow + rl) * HID + cb;
            size_t o1 = (size_t)(blockRow + rl + 8) * HID + cb;
            *reinterpret_cast<float2*>(out + o0) = make_float2(z0, z1);
            *reinterpret_cast<float2*>(out + o1) = make_float2(z2, z3);
        }
    }

    // ================= pass 2: r = hardsigmoid(ih @ Wr^T + br); A_h := tf32(r * h) ======
    gemm_pass(Asu, Bsu, bs_byte, wscratch + NCH * CHW, acc, m0, n0, lane, tid);
    // gemm_pass ends with __syncthreads(): all warps done reading A; safe to rewrite.
    float* Asf = reinterpret_cast<float*>(Asu);
    #pragma unroll
    for (int mt = 0; mt < 4; mt++) {
        int rl = m0 + mt * 16 + (lane >> 2);
        int xr = (rl & 7) << 2;
        #pragma unroll
        for (int nt = 0; nt < 8; nt++) {
            int cb = n0 + nt * 8 + ((lane & 3) << 1);
            float2 bv = *reinterpret_cast<const float2*>(br + cb);
            float r0 = __saturatef((acc[mt][nt][0] + bv.x) * 0.16666667f + 0.5f);
            float r1 = __saturatef((acc[mt][nt][1] + bv.y) * 0.16666667f + 0.5f);
            float r2 = __saturatef((acc[mt][nt][2] + bv.x) * 0.16666667f + 0.5f);
            float r3 = __saturatef((acc[mt][nt][3] + bv.y) * 0.16666667f + 0.5f);
            int w0 = rl * CAT + ((INP + cb) ^ xr);
            int w1 = (rl + 8) * CAT + ((INP + cb) ^ xr);
            Asu[w0]     = f2tf32(r0 * Asf[w0]);
            Asu[w0 + 1] = f2tf32(r1 * Asf[w0 + 1]);
            Asu[w1]     = f2tf32(r2 * Asf[w1]);
            Asu[w1 + 1] = f2tf32(r3 * Asf[w1 + 1]);
        }
    }
    __syncthreads();

    // ================= pass 3: htilde; h_next = z*h + (1-z)*hardtanh(.) =================
    gemm_pass(Asu, Bsu, bs_byte, wscratch + 2 * NCH * CHW, acc, m0, n0, lane, tid);
    #pragma unroll
    for (int mt = 0; mt < 4; mt++) {
        int rl = m0 + mt * 16 + (lane >> 2);
        #pragma unroll
        for (int nt = 0; nt < 8; nt++) {
            int cb = n0 + nt * 8 + ((lane & 3) << 1);
            float2 bv = *reinterpret_cast<const float2*>(bh + cb);
            size_t o0 = (size_t)(blockRow + rl) * HID + cb;
            size_t o1 = (size_t)(blockRow + rl + 8) * HID + cb;
            float2 zz0 = *reinterpret_cast<const float2*>(out + o0);  // z written by this thread
            float2 zz1 = *reinterpret_cast<const float2*>(out + o1);
            float2 hh0 = *reinterpret_cast<const float2*>(hp + o0);
            float2 hh1 = *reinterpret_cast<const float2*>(hp + o1);
            float t0 = fminf(fmaxf(acc[mt][nt][0] + bv.x, -1.f), 1.f);
            float t1 = fminf(fmaxf(acc[mt][nt][1] + bv.y, -1.f), 1.f);
            float t2 = fminf(fmaxf(acc[mt][nt][2] + bv.x, -1.f), 1.f);
            float t3 = fminf(fmaxf(acc[mt][nt][3] + bv.y, -1.f), 1.f);
            float2 r0, r1;
            r0.x = zz0.x * hh0.x + (1.f - zz0.x) * t0;
            r0.y = zz0.y * hh0.y + (1.f - zz0.y) * t1;
            r1.x = zz1.x * hh1.x + (1.f - zz1.x) * t2;
            r1.y = zz1.y * hh1.y + (1.f - zz1.y) * t3;
            *reinterpret_cast<float2*>(out + o0) = r0;
            *reinterpret_cast<float2*>(out + o1) = r1;
        }
    }
}

extern "C" void kernel_launch(void* const* d_in, const int* in_sizes, int n_in,
                              void* d_out, int out_size) {
    const float* x  = (const float*)d_in[0];
    const float* hp = (const float*)d_in[1];
    const float* Wz = (const float*)d_in[2];
    const float* bz = (const float*)d_in[3];
    const float* Wr = (const float*)d_in[4];
    const float* br = (const float*)d_in[5];
    const float* Wh = (const float*)d_in[6];
    const float* bh = (const float*)d_in[7];
    float* out = (float*)d_out;

    preconv_kernel<<<(3 * NCH * CHW + THREADS - 1) / THREADS, THREADS>>>(Wz, Wr, Wh);

    int batch = in_sizes[0] / INP;
    int grid = batch / TM;
    size_t smem = (size_t)(TM * CAT + 2 * CHW) * 4;   // 229376 B
    cudaFuncSetAttribute(gru_main_kernel,
                         cudaFuncAttributeMaxDynamicSharedMemorySize, (int)smem);
    gru_main_kernel<<<grid, THREADS, smem>>>(x, hp, bz, br, bh, out);
}

// round 4
// speedup vs baseline: 1.1850x; 1.1850x over previous
#include <cuda_runtime.h>
#include <cstdint>

#define THREADS 256
#define TM      64         // batch rows per CTA
#define HID     256
#define INP     128
#define CAT     384
#define NCH     48         // K chunks of 8
#define CHW     2048       // words per chunk (256 n x 8 k)
#define CHB     8192       // bytes per chunk

// Pre-converted (tf32, pair-interleaved) weights: [Wz | Wr | Wh], each NCH*CHW words.
// chunk layout: word = n*8 + p, p = 2*(kl&3) + (kl>>2), kl = k - chunk*8
__device__ uint32_t wscratch[3 * NCH * CHW];

static __device__ __forceinline__ uint32_t smem_u32(const void* p) {
    uint32_t a;
    asm("{ .reg .u64 t; cvta.to.shared.u64 t, %1; cvt.u32.u64 %0, t; }" : "=r"(a) : "l"(p));
    return a;
}
static __device__ __forceinline__ uint64_t gptr(const void* p) {
    uint64_t r;
    asm("cvta.to.global.u64 %0, %1;" : "=l"(r) : "l"(p));
    return r;
}
static __device__ __forceinline__ uint32_t f2tf32(float v) {
    uint32_t t;
    asm("cvt.rna.tf32.f32 %0, %1;" : "=r"(t) : "f"(v));
    return t;
}
// A smem word offset for (row r, k): pair-interleaved within 8-groups + XOR swizzle
static __device__ __forceinline__ int a_off(int r, int k) {
    int g = k >> 3, kl = k & 7;
    int p = 2 * (kl & 3) + (kl >> 2);
    return r * CAT + ((g * 8 + p) ^ ((r & 3) << 3));
}
static __device__ __forceinline__ void mma8(float* d, uint32_t a0, uint32_t a1,
                                            uint32_t a2, uint32_t a3,
                                            uint32_t b0, uint32_t b1) {
    asm volatile(
        "mma.sync.aligned.m16n8k8.row.col.f32.tf32.tf32.f32 "
        "{%0,%1,%2,%3}, {%4,%5,%6,%7}, {%8,%9}, {%0,%1,%2,%3};"
        : "+f"(d[0]), "+f"(d[1]), "+f"(d[2]), "+f"(d[3])
        : "r"(a0), "r"(a1), "r"(a2), "r"(a3), "r"(b0), "r"(b1));
}
static __device__ __forceinline__ void cpa16(uint32_t saddr, uint64_t gaddr) {
    asm volatile("cp.async.ca.shared.global [%0], [%1], 16;" :: "r"(saddr), "l"(gaddr) : "memory");
}
#define CP_COMMIT() asm volatile("cp.async.commit_group;" ::: "memory")
#define CP_WAIT(n)  asm volatile("cp.async.wait_group %0;" :: "n"(n) : "memory")

// load one 8KB chunk: 2 x 16B per thread
static __device__ __forceinline__ void load_chunk(uint32_t sdst, uint64_t gsrc, int tid) {
    cpa16(sdst + tid * 32,      gsrc + (size_t)tid * 32);
    cpa16(sdst + tid * 32 + 16, gsrc + (size_t)tid * 32 + 16);
    CP_COMMIT();
}

// ---------------- weight pre-conversion: fp32 -> tf32, pair-interleaved chunk image -----
__global__ void preconv_kernel(const float* __restrict__ Wz, const float* __restrict__ Wr,
                               const float* __restrict__ Wh) {
    int gid = blockIdx.x * THREADS + threadIdx.x;
    if (gid >= 3 * NCH * CHW) return;
    int w = gid / (NCH * CHW);
    int rem = gid - w * (NCH * CHW);
    int c = rem >> 11;            // / 2048
    int widx = rem & 2047;
    int n = widx >> 3;
    int p = widx & 7;
    int kl = (p >> 1) + ((p & 1) << 2);
    int k = c * 8 + kl;
    const float* W = (w == 0) ? Wz : (w == 1) ? Wr : Wh;
    wscratch[gid] = f2tf32(W[(size_t)n * CAT + k]);
}

// ---------------- one K=384 GEMM pass: CTA tile 64x256, warp tile 32x64 -----------------
static __device__ __forceinline__ void gemm_pass(
    const uint32_t* Asu, const uint32_t* Bsu, uint32_t bs_byte,
    const uint32_t* wbase, float (&acc)[2][8][4],
    int m0, int n0, int lane, int tid)
{
    #pragma unroll
    for (int mt = 0; mt < 2; mt++)
        #pragma unroll
        for (int nt = 0; nt < 8; nt++)
            #pragma unroll
            for (int q = 0; q < 4; q++) acc[mt][nt][q] = 0.f;

    uint64_t g0 = gptr(wbase);
    load_chunk(bs_byte, g0, tid);

    const int rq = lane >> 2;       // 0..7
    const int kq = lane & 3;        // 0..3

    #pragma unroll 1
    for (int c = 0; c < NCH; c++) {
        if (c + 1 < NCH) {
            load_chunk(bs_byte + ((c + 1) & 1) * CHB, g0 + (size_t)(c + 1) * CHB, tid);
            CP_WAIT(1);
        } else {
            CP_WAIT(0);
        }
        __syncthreads();

        const uint32_t* B = Bsu + (c & 1) * CHW;
        // B fragments: LDS.64 gives (k=kq, k=kq+4) for column n
        uint32_t bf[8][2];
        #pragma unroll
        for (int nt = 0; nt < 8; nt++) {
            int n = n0 + nt * 8 + rq;
            uint2 v = *reinterpret_cast<const uint2*>(B + n * 8 + 2 * kq);
            bf[nt][0] = v.x; bf[nt][1] = v.y;
        }
        #pragma unroll
        for (int mt = 0; mt < 2; mt++) {
            int r = m0 + mt * 16 + rq;
            int xr = (r & 3) << 3;                      // (r+8)&3 == r&3
            uint2 lo = *reinterpret_cast<const uint2*>(Asu + r * CAT + ((c * 8 + 2 * kq) ^ xr));
            uint2 hi = *reinterpret_cast<const uint2*>(Asu + (r + 8) * CAT + ((c * 8 + 2 * kq) ^ xr));
            #pragma unroll
            for (int nt = 0; nt < 8; nt++)
                mma8(acc[mt][nt], lo.x, hi.x, lo.y, hi.y, bf[nt][0], bf[nt][1]);
        }
        __syncthreads();
    }
}

// ---------------- fused GRU kernel ------------------------------------------------------
__global__ void __launch_bounds__(THREADS, 2) gru_main_kernel(
    const float* __restrict__ x, const float* __restrict__ hp,
    const float* __restrict__ bz, const float* __restrict__ br,
    const float* __restrict__ bh, float* __restrict__ out)
{
    extern __shared__ uint32_t sm[];
    uint32_t* Asu = sm;                       // 64*384 words (tf32 ih, interleave+swizzle)
    uint32_t* Bsu = sm + TM * CAT;            // 2 * 2048 words (B double buffer)
    const uint32_t bs_byte = smem_u32(Bsu);

    const int tid  = threadIdx.x;
    const int lane = tid & 31;
    const int warp = tid >> 5;
    const int m0   = (warp >> 2) * 32;
    const int n0   = (warp & 3) * 64;
    const int blockRow = blockIdx.x * TM;

    // ---- fill A smem: tf32(ih); thread handles one 8-k group per iter ----
    #pragma unroll 1
    for (int it = 0; it < 12; it++) {
        int idx = it * THREADS + tid;          // 0 .. 3071 groups
        int row = idx / 48;
        int g8  = idx - row * 48;
        int k0  = g8 * 8;
        const float* src = (k0 < INP) ? (x + (size_t)(blockRow + row) * INP + k0)
                                      : (hp + (size_t)(blockRow + row) * HID + (k0 - INP));
        float4 v0 = *reinterpret_cast<const float4*>(src);
        float4 v1 = *reinterpret_cast<const float4*>(src + 4);
        uint4 u0, u1;   // positions [k0,k4,k1,k5] and [k2,k6,k3,k7]
        u0.x = f2tf32(v0.x); u0.y = f2tf32(v1.x); u0.z = f2tf32(v0.y); u0.w = f2tf32(v1.y);
        u1.x = f2tf32(v0.z); u1.y = f2tf32(v1.z); u1.z = f2tf32(v0.w); u1.w = f2tf32(v1.w);
        int base = row * CAT + ((g8 * 8) ^ ((row & 3) << 3));
        *reinterpret_cast<uint4*>(Asu + base)     = u0;
        *reinterpret_cast<uint4*>(Asu + base + 4) = u1;
    }
    __syncthreads();

    float acc[2][8][4];

    // ================= pass 1: z = hardsigmoid(ih @ Wz^T + bz) -> out (scratch) =========
    gemm_pass(Asu, Bsu, bs_byte, wscratch, acc, m0, n0, lane, tid);
    #pragma unroll
    for (int mt = 0; mt < 2; mt++) {
        int rl = m0 + mt * 16 + (lane >> 2);
        #pragma unroll
        for (int nt = 0; nt < 8; nt++) {
            int cb = n0 + nt * 8 + ((lane & 3) << 1);
            float2 bv = *reinterpret_cast<const float2*>(bz + cb);
            float z0 = __saturatef((acc[mt][nt][0] + bv.x) * 0.16666667f + 0.5f);
            float z1 = __saturatef((acc[mt][nt][1] + bv.y) * 0.16666667f + 0.5f);
            float z2 = __saturatef((acc[mt][nt][2] + bv.x) * 0.16666667f + 0.5f);
            float z3 = __saturatef((acc[mt][nt][3] + bv.y) * 0.16666667f + 0.5f);
            size_t o0 = (size_t)(blockRow + rl) * HID + cb;
            size_t o1 = (size_t)(blockRow + rl + 8) * HID + cb;
            *reinterpret_cast<float2*>(out + o0) = make_float2(z0, z1);
            *reinterpret_cast<float2*>(out + o1) = make_float2(z2, z3);
        }
    }

    // ================= pass 2: r = hardsigmoid(ih @ Wr^T + br); A_h := tf32(r * h) ======
    gemm_pass(Asu, Bsu, bs_byte, wscratch + NCH * CHW, acc, m0, n0, lane, tid);
    // gemm_pass ends with __syncthreads(): all warps done reading A; safe to rewrite.
    const float* Asf = reinterpret_cast<const float*>(Asu);
    #pragma unroll
    for (int mt = 0; mt < 2; mt++) {
        int rl = m0 + mt * 16 + (lane >> 2);
        #pragma unroll
        for (int nt = 0; nt < 8; nt++) {
            int cb = n0 + nt * 8 + ((lane & 3) << 1);
            float2 bv = *reinterpret_cast<const float2*>(br + cb);
            float r0 = __saturatef((acc[mt][nt][0] + bv.x) * 0.16666667f + 0.5f);
            float r1 = __saturatef((acc[mt][nt][1] + bv.y) * 0.16666667f + 0.5f);
            float r2 = __saturatef((acc[mt][nt][2] + bv.x) * 0.16666667f + 0.5f);
            float r3 = __saturatef((acc[mt][nt][3] + bv.y) * 0.16666667f + 0.5f);
            int kA = INP + cb;
            int o00 = a_off(rl, kA),     o01 = a_off(rl, kA + 1);
            int o10 = a_off(rl + 8, kA), o11 = a_off(rl + 8, kA + 1);
            Asu[o00] = f2tf32(r0 * Asf[o00]);
            Asu[o01] = f2tf32(r1 * Asf[o01]);
            Asu[o10] = f2tf32(r2 * Asf[o10]);
            Asu[o11] = f2tf32(r3 * Asf[o11]);
        }
    }
    __syncthreads();

    // ================= pass 3: htilde; h_next = z*h + (1-z)*hardtanh(.) =================
    gemm_pass(Asu, Bsu, bs_byte, wscratch + 2 * NCH * CHW, acc, m0, n0, lane, tid);
    #pragma unroll
    for (int mt = 0; mt < 2; mt++) {
        int rl = m0 + mt * 16 + (lane >> 2);
        #pragma unroll
        for (int nt = 0; nt < 8; nt++) {
            int cb = n0 + nt * 8 + ((lane & 3) << 1);
            float2 bv = *reinterpret_cast<const float2*>(bh + cb);
            size_t o0 = (size_t)(blockRow + rl) * HID + cb;
            size_t o1 = (size_t)(blockRow + rl + 8) * HID + cb;
            float2 zz0 = *reinterpret_cast<const float2*>(out + o0);  // z written by this thread
            float2 zz1 = *reinterpret_cast<const float2*>(out + o1);
            float2 hh0 = *reinterpret_cast<const float2*>(hp + o0);
            float2 hh1 = *reinterpret_cast<const float2*>(hp + o1);
            float t0 = fminf(fmaxf(acc[mt][nt][0] + bv.x, -1.f), 1.f);
            float t1 = fminf(fmaxf(acc[mt][nt][1] + bv.y, -1.f), 1.f);
            float t2 = fminf(fmaxf(acc[mt][nt][2] + bv.x, -1.f), 1.f);
            float t3 = fminf(fmaxf(acc[mt][nt][3] + bv.y, -1.f), 1.f);
            float2 r0, r1;
            r0.x = zz0.x * hh0.x + (1.f - zz0.x) * t0;
            r0.y = zz0.y * hh0.y + (1.f - zz0.y) * t1;
            r1.x = zz1.x * hh1.x + (1.f - zz1.x) * t2;
            r1.y = zz1.y * hh1.y + (1.f - zz1.y) * t3;
            *reinterpret_cast<float2*>(out + o0) = r0;
            *reinterpret_cast<float2*>(out + o1) = r1;
        }
    }
}

extern "C" void kernel_launch(void* const* d_in, const int* in_sizes, int n_in,
                              void* d_out, int out_size) {
    const float* x  = (const float*)d_in[0];
    const float* hp = (const float*)d_in[1];
    const float* Wz = (const float*)d_in[2];
    const float* bz = (const float*)d_in[3];
    const float* Wr = (const float*)d_in[4];
    const float* br = (const float*)d_in[5];
    const float* Wh = (const float*)d_in[6];
    const float* bh = (const float*)d_in[7];
    float* out = (float*)d_out;

    preconv_kernel<<<(3 * NCH * CHW + THREADS - 1) / THREADS, THREADS>>>(Wz, Wr, Wh);

    int batch = in_sizes[0] / INP;
    int grid = batch / TM;
    size_t smem = (size_t)(TM * CAT + 2 * CHW) * 4;   // 114688 B = 112 KB
    cudaFuncSetAttribute(gru_main_kernel,
                         cudaFuncAttributeMaxDynamicSharedMemorySize, (int)smem);
    gru_main_kernel<<<grid, THREADS, smem>>>(x, hp, bz, br, bh, out);
}